// round 16
// baseline (speedup 1.0000x reference)
#include <cuda_runtime.h>
#include <cuda_bf16.h>
#include <math.h>
#include <stdint.h>

// ---------------- problem constants ----------------
#define Bb    2
#define Nn    6
#define BN12  (Bb*Nn)          // 12
#define FCc   256
#define FHh   32
#define FWw   88
#define P2    (FHh*FWw)        // 2816
#define NPIX  (BN12*P2)        // 33792
#define Dd    20
#define OUTC  128
#define C3    (OUTC+2)         // 130
#define NX    256
#define NY    256
#define BEV_ELEMS ((size_t)Bb*OUTC*NX*NY)
#define MASK_ELEMS ((size_t)Bb*NX*NY)
#define KTOT  (FCc*9)          // 2304
#define KC    64               // k-chunk per stage
#define NSTAGE (KTOT/KC)       // 36
#define NPTS  (Bb*Nn*Dd*FHh*FWw)  // 675840
// padded activation layout
#define PH    34
#define PW    96
#define PP2   (PH*PW)          // 3264
#define CSZI  (BN12*FCc*PP2)   // 10,027,008 elements per copy

// ---------------- device scratch ----------------
__device__ __align__(16) float g_buf2[(size_t)BN12*FCc*P2];        // conv2 out (f32)
__device__ __align__(16) __nv_bfloat16 g_x1h[(size_t)3*CSZI];      // conv1 input hi, 3 tap copies
__device__ __align__(16) __nv_bfloat16 g_x1l[(size_t)3*CSZI];
__device__ __align__(16) __nv_bfloat16 g_x2h[(size_t)3*CSZI];      // conv2 input hi, 3 tap copies
__device__ __align__(16) __nv_bfloat16 g_x2l[(size_t)3*CSZI];
__device__ __align__(16) __nv_bfloat16 g_w1h[(size_t)FCc*KTOT];
__device__ __align__(16) __nv_bfloat16 g_w1l[(size_t)FCc*KTOT];
__device__ __align__(16) __nv_bfloat16 g_w2h[(size_t)FCc*KTOT];
__device__ __align__(16) __nv_bfloat16 g_w2l[(size_t)FCc*KTOT];
__device__ __align__(16) float g_featsT[(size_t)BN12*P2*OUTC];
__device__ __align__(16) float g_gbuf[(size_t)BN12*Dd*P2];
__device__ __align__(16) float g_bevT[(size_t)Bb*NX*NY*OUTC];
__device__ __align__(16) unsigned char g_maskbuf[Bb*NX*NY];
__device__ float g_matsf[BN12*24];

// ---------------- helpers ----------------
__device__ __forceinline__ uint32_t smem_u32(const void* p){
    uint32_t a;
    asm("{ .reg .u64 t; cvta.to.shared.u64 t, %1; cvt.u32.u64 %0, t; }" : "=r"(a) : "l"(p));
    return a;
}
__device__ __forceinline__ void ldsm_x4(uint32_t &r0,uint32_t &r1,uint32_t &r2,uint32_t &r3, uint32_t a){
    asm volatile("ldmatrix.sync.aligned.m8n8.x4.shared.b16 {%0,%1,%2,%3}, [%4];"
        : "=r"(r0),"=r"(r1),"=r"(r2),"=r"(r3) : "r"(a));
}
__device__ __forceinline__ void ldsm_x4_t(uint32_t &r0,uint32_t &r1,uint32_t &r2,uint32_t &r3, uint32_t a){
    asm volatile("ldmatrix.sync.aligned.m8n8.x4.trans.shared.b16 {%0,%1,%2,%3}, [%4];"
        : "=r"(r0),"=r"(r1),"=r"(r2),"=r"(r3) : "r"(a));
}
__device__ __forceinline__ void mma_bf16(float* c, const uint32_t* a, const uint32_t* b){
    asm volatile("mma.sync.aligned.m16n8k16.row.col.f32.bf16.bf16.f32 "
        "{%0,%1,%2,%3}, {%4,%5,%6,%7}, {%8,%9}, {%0,%1,%2,%3};"
        : "+f"(c[0]),"+f"(c[1]),"+f"(c[2]),"+f"(c[3])
        : "r"(a[0]),"r"(a[1]),"r"(a[2]),"r"(a[3]), "r"(b[0]),"r"(b[1]));
}
__device__ __forceinline__ void cp_async16(uint32_t dst, const void* src){
    asm volatile("cp.async.cg.shared.global [%0], [%1], 16;" :: "r"(dst), "l"(src));
}
__device__ __forceinline__ void cp_commit(){ asm volatile("cp.async.commit_group;"); }
__device__ __forceinline__ void cp_wait0(){ asm volatile("cp.async.wait_group 0;"); }
__device__ __forceinline__ void red_add_v4(float* p, float x, float y, float z, float w){
    asm volatile("red.global.add.v4.f32 [%0], {%1,%2,%3,%4};"
                 :: "l"(p), "f"(x), "f"(y), "f"(z), "f"(w) : "memory");
}
__device__ __forceinline__ void split2(float a, float b, uint32_t &hh, uint32_t &ll){
    __nv_bfloat16 ha = __float2bfloat16(a);
    __nv_bfloat16 hb = __float2bfloat16(b);
    __nv_bfloat16 la = __float2bfloat16(a - __bfloat162float(ha));
    __nv_bfloat16 lb = __float2bfloat16(b - __bfloat162float(hb));
    hh = (uint32_t)__bfloat16_as_ushort(ha) | ((uint32_t)__bfloat16_as_ushort(hb) << 16);
    ll = (uint32_t)__bfloat16_as_ushort(la) | ((uint32_t)__bfloat16_as_ushort(lb) << 16);
}

// ---------------- f32 3x3 inverse, cuSOLVER-style (FROZEN) ----------------
__device__ __forceinline__ void lu_inv3x3_cusolver(const float* A, float* X){
    float a00=A[0],a01=A[1],a02=A[2],a10=A[3],a11=A[4],a12=A[5],a20=A[6],a21=A[7],a22=A[8];
    float r0 = __fdiv_rn(1.0f, a00);
    float l10 = __fmul_rn(a10, r0);
    float l20 = __fmul_rn(a20, r0);
    float u11 = fmaf(-l10, a01, a11);
    float u12 = fmaf(-l10, a02, a12);
    float t21 = fmaf(-l20, a01, a21);
    float u22t= fmaf(-l20, a02, a22);
    float r1 = __fdiv_rn(1.0f, u11);
    float l21 = __fmul_rn(t21, r1);
    float u22 = fmaf(-l21, u12, u22t);
    float r2 = __fdiv_rn(1.0f, u22);
#pragma unroll
    for (int j=0;j<3;j++){
        float e0 = (j==0)?1.f:0.f, e1=(j==1)?1.f:0.f, e2=(j==2)?1.f:0.f;
        float y0 = e0;
        float y1 = fmaf(-l10, y0, e1);
        float y2 = fmaf(-l21, y1, fmaf(-l20, y0, e2));
        float x2 = __fmul_rn(y2, r2);
        float x1 = __fmul_rn(fmaf(-u12, x2, y1), r1);
        float x0 = __fmul_rn(fmaf(-a02, x2, fmaf(-a01, x1, y0)), r0);
        X[0*3+j]=x0; X[1*3+j]=x1; X[2*3+j]=x2;
    }
}

__global__ void setup_mats(const float* __restrict__ rot, const float* __restrict__ tr,
                           const float* __restrict__ intr,
                           const float* __restrict__ prot, const float* __restrict__ ptr_){
    int i = threadIdx.x;
    if (i >= BN12) return;
    float IP[9], IK[9];
    lu_inv3x3_cusolver(prot + i*9, IP);
    lu_inv3x3_cusolver(intr + i*9, IK);
    float* M = g_matsf + i*24;
#pragma unroll
    for (int j=0;j<9;j++) M[j]=IP[j];
#pragma unroll
    for (int r=0;r<3;r++)
#pragma unroll
        for (int c=0;c<3;c++){
            float acc = __fmul_rn(rot[i*9+r*3+0], IK[0*3+c]);
            acc = fmaf(rot[i*9+r*3+1], IK[1*3+c], acc);
            acc = fmaf(rot[i*9+r*3+2], IK[2*3+c], acc);
            M[9+r*3+c]=acc;
        }
#pragma unroll
    for (int j=0;j<3;j++){ M[18+j]=ptr_[i*3+j]; M[21+j]=tr[i*3+j]; }
}

// ---------------- prep: weight splits + conv1-input padded tap copies ----------------
__global__ void prep_all(const float* __restrict__ w1, const float* __restrict__ w2,
                         const float* __restrict__ img){
    int i = blockIdx.x*blockDim.x + threadIdx.x;
    int stride = gridDim.x*blockDim.x;
    const int NW = FCc*KTOT;
    for (int k = i; k < NW; k += stride){
        float x1 = w1[k];
        __nv_bfloat16 h1 = __float2bfloat16(x1);
        g_w1h[k] = h1;
        g_w1l[k] = __float2bfloat16(x1 - __bfloat162float(h1));
        float x2 = w2[k];
        __nv_bfloat16 h2 = __float2bfloat16(x2);
        g_w2h[k] = h2;
        g_w2l[k] = __float2bfloat16(x2 - __bfloat162float(h2));
    }
    for (int idx = i; idx < CSZI; idx += stride){
        int bnc = idx / PP2; int r = idx - bnc*PP2;
        int hp = r / PW; int wc = r - hp*PW;
        int h = hp - 1;
#pragma unroll
        for (int j = 0; j < 3; ++j){
            int w = wc + j - 1;
            float v = (h>=0 && h<FHh && w>=0 && w<FWw) ? img[(size_t)bnc*P2 + h*FWw + w] : 0.f;
            __nv_bfloat16 hh = __float2bfloat16(v);
            g_x1h[(size_t)j*CSZI + idx] = hh;
            g_x1l[(size_t)j*CSZI + idx] = __float2bfloat16(v - __bfloat162float(hh));
        }
    }
}

// ---------------- zero: bev scratch + conv2 center-copy borders ----------------
__global__ void zero_kernel(){
    size_t tid = (size_t)blockIdx.x*blockDim.x + threadIdx.x;
    size_t stride = (size_t)gridDim.x*blockDim.x;
    float4* bp = (float4*)g_bevT;
    const size_t n4 = BEV_ELEMS/4;
    for (size_t i=tid;i<n4;i+=stride) bp[i]=make_float4(0.f,0.f,0.f,0.f);
    uint4* mp = (uint4*)g_maskbuf;
    const size_t nm = MASK_ELEMS/16;
    for (size_t i=tid;i<nm;i+=stride) mp[i]=make_uint4(0u,0u,0u,0u);
    // conv2 center copy (j=1) borders: rows 0,33 full; cols 88..95 for hp 1..32
    const __nv_bfloat16 z = __ushort_as_bfloat16((unsigned short)0);
    const int NB = BN12*FCc*448;
    for (size_t t=tid; t<(size_t)NB; t+=stride){
        int bnc = (int)(t / 448); int s = (int)(t - (size_t)bnc*448);
        int off;
        if (s < 96) off = s;
        else if (s < 192) off = 33*PW + (s-96);
        else { int q = s - 192; off = (1 + (q>>3))*PW + 88 + (q & 7); }
        size_t e = (size_t)CSZI + (size_t)bnc*PP2 + off;
        g_x2h[e] = z; g_x2l[e] = z;
    }
}

// ---------------- replicate: conv2 copies j=0,2 from center copy (flat shift) ----------------
__global__ void replicate_x2(){
    int i = blockIdx.x*blockDim.x + threadIdx.x;
    int stride = gridDim.x*blockDim.x;
    const __nv_bfloat16 z = __ushort_as_bfloat16((unsigned short)0);
    for (int f = i; f < CSZI; f += stride){
        __nv_bfloat16 hm = (f >= 1)       ? g_x2h[(size_t)CSZI + f - 1] : z;
        __nv_bfloat16 hp_ = (f+1 < CSZI)  ? g_x2h[(size_t)CSZI + f + 1] : z;
        __nv_bfloat16 lm = (f >= 1)       ? g_x2l[(size_t)CSZI + f - 1] : z;
        __nv_bfloat16 lp_ = (f+1 < CSZI)  ? g_x2l[(size_t)CSZI + f + 1] : z;
        g_x2h[f] = hm;  g_x2h[(size_t)2*CSZI + f] = hp_;
        g_x2l[f] = lm;  g_x2l[(size_t)2*CSZI + f] = lp_;
    }
}

// ---------------- bf16-split implicit conv GEMM, 2 CTA/SM, all-async loads ----------------
// A smem: [128 co][64 k] 128B SW128 rows (hi+lo).  B smem: [64 k][128 pix] 256B rows,
// per-k xor swizzle, filled by cp.async.16 from padded tap copies, read via ldmatrix.trans.
#define OFF_AHI   0
#define OFF_ALO   16384
#define OFF_BHI   32768
#define OFF_BLO   49152
#define STAGE_BYTES 65536
#define KTAB_OFF  STAGE_BYTES              // 65536
#define CONV_SMEM (KTAB_OFF + KTOT*4)      // 74752

template<int EPI> // 0: bf16 hi/lo padded center-copy out ; 1: f32 out
__global__ void __launch_bounds__(256, 2)
conv_mma(const __nv_bfloat16* __restrict__ Xh, const __nv_bfloat16* __restrict__ Xl,
         const __nv_bfloat16* __restrict__ Wh, const __nv_bfloat16* __restrict__ Wl,
         const float* __restrict__ cb,
         const float* __restrict__ bs, const float* __restrict__ bbp,
         const float* __restrict__ bm, const float* __restrict__ bv,
         __nv_bfloat16* __restrict__ OutH, __nv_bfloat16* __restrict__ OutL,
         float* __restrict__ OutF)
{
    extern __shared__ char smbuf[];
    const uint32_t sb = smem_u32(smbuf);
    uint32_t* ktab = (uint32_t*)(smbuf + KTAB_OFF);
    const int tid = threadIdx.x;
    const int wid = tid >> 5;
    const int lane = tid & 31;

    const int tileP = blockIdx.x;              // 0..263
    const int m0 = blockIdx.y * 128;           // co tile base
    const int bn = tileP / 22;
    const int p0 = (tileP - bn*22) * 128;

    // ---- build k-offset table: entry = j*CSZI + ci*PP2 + kh*PW  (j = kw) ----
    for (int k = tid; k < KTOT; k += 256){
        int ci = k / 9; int r = k - 9*ci;
        int kh = r / 3; int kw = r - 3*kh;
        ktab[k] = (uint32_t)(kw*CSZI + ci*PP2 + kh*PW);
    }

    // warp tiling: 2 (M) x 4 (N)
    const int wm = wid & 1, wn = wid >> 1;
    const int m_w = wm * 64, n_w = wn * 32;

    float acc[4][4][4];
#pragma unroll
    for (int a=0;a<4;a++)
#pragma unroll
        for (int b=0;b<4;b++)
#pragma unroll
            for (int c=0;c<4;c++) acc[a][b][c]=0.f;

    // ---- B producer coords: thread handles (k = wid*8+i, 8-pixel group pg, plane) ----
    const int pg = lane & 15;
    const int plane = lane >> 4;
    const size_t bnoff = (size_t)bn * FCc * PP2;
    const __nv_bfloat16* Xpb = (plane ? Xl : Xh) + bnoff;
    int pp = p0 + pg*8;
    int phh = pp / FWw;
    const int hwoff = phh*PW + (pp - phh*FWw);
    const uint32_t dstb2 = sb + OFF_BHI + (uint32_t)(plane*16384);
    const uint32_t pgx = (uint32_t)(pg << 4);

    // ---- A producer coords (R12 scheme) ----
    const int a_row  = tid >> 1;
    const int a_half = (tid & 1) * 64;
    const __nv_bfloat16* wh_row = Wh + (size_t)(m0 + a_row)*KTOT + (a_half >> 1);
    const __nv_bfloat16* wl_row = Wl + (size_t)(m0 + a_row)*KTOT + (a_half >> 1);
    uint32_t asto[4];
#pragma unroll
    for (int i=0;i<4;i++)
        asto[i] = (uint32_t)(a_row*128) + ((uint32_t)(a_half + i*16) ^ ((uint32_t)(a_row & 7) << 4));

    // ---- consumer A ldsm (unchanged) ----
    const int lr = lane & 15;
    const int khalf16 = (lane >> 4) * 16;
    const uint32_t lx = (uint32_t)((lane & 7) << 4);
    uint32_t kxv[4];
#pragma unroll
    for (int kk=0;kk<4;kk++) kxv[kk] = (uint32_t)(kk*32 + khalf16) ^ lx;
    uint32_t amb[4];
#pragma unroll
    for (int mt=0;mt<4;mt++) amb[mt] = (uint32_t)((m_w + mt*16 + lr)*128);
    // ---- consumer B trans-ldsm ----
    const int setq = lane >> 3, rr = lane & 7;
    const uint32_t bconst = (uint32_t)((((setq & 2) ? 8 : 0) + rr) * 256);
    uint32_t pbx[2];
#pragma unroll
    for (int nt2=0;nt2<2;nt2++)
        pbx[nt2] = ((uint32_t)((n_w + nt2*16 + ((setq & 1) ? 8 : 0)) * 2)) ^ ((uint32_t)(rr << 4));
    const uint32_t sbB = sb + OFF_BHI;

#pragma unroll 1
    for (int s = 0; s < NSTAGE; ++s){
        __syncthreads();            // compute(s-1) done, safe to overwrite

        // ---- A: cp.async weights ----
        {
            const __nv_bfloat16* srcH = wh_row + s*KC;
            const __nv_bfloat16* srcL = wl_row + s*KC;
#pragma unroll
            for (int i=0;i<4;i++){
                cp_async16(sb + OFF_AHI + asto[i], srcH + i*8);
                cp_async16(sb + OFF_ALO + asto[i], srcL + i*8);
            }
        }
        // ---- B: cp.async from padded tap copies ----
        {
            const uint32_t* tp = &ktab[s*KC + wid*8];
            uint4 t0 = *(const uint4*)tp;
            uint4 t1 = *(const uint4*)(tp + 4);
            uint32_t te[8] = {t0.x,t0.y,t0.z,t0.w,t1.x,t1.y,t1.z,t1.w};
#pragma unroll
            for (int i=0;i<8;i++){
                uint32_t dst = dstb2 + (uint32_t)((wid*8 + i)*256) + (pgx ^ ((uint32_t)i << 4));
                cp_async16(dst, Xpb + te[i] + hwoff);
            }
        }
        cp_commit();
        cp_wait0();
        __syncthreads();

        // ---- compute stage s: 4 k-steps of 16 ----
#pragma unroll
        for (int kk = 0; kk < 4; ++kk){
            uint32_t ah[4][4], al[4][4];
#pragma unroll
            for (int mt = 0; mt < 4; ++mt){
                uint32_t a = sb + OFF_AHI + amb[mt] + kxv[kk];
                ldsm_x4(ah[mt][0], ah[mt][1], ah[mt][2], ah[mt][3], a);
                ldsm_x4(al[mt][0], al[mt][1], al[mt][2], al[mt][3], a + 16384);
            }
            uint32_t bh[4][2], bl[4][2];
#pragma unroll
            for (int nt2 = 0; nt2 < 2; ++nt2){
                uint32_t a = sbB + (uint32_t)(kk*4096) + bconst + pbx[nt2];
                uint32_t r0,r1,r2,r3;
                ldsm_x4_t(r0,r1,r2,r3, a);
                bh[nt2*2+0][0]=r0; bh[nt2*2+0][1]=r2;
                bh[nt2*2+1][0]=r1; bh[nt2*2+1][1]=r3;
                ldsm_x4_t(r0,r1,r2,r3, a + 16384);
                bl[nt2*2+0][0]=r0; bl[nt2*2+0][1]=r2;
                bl[nt2*2+1][0]=r1; bl[nt2*2+1][1]=r3;
            }
#pragma unroll
            for (int mt = 0; mt < 4; ++mt)
#pragma unroll
                for (int nt = 0; nt < 4; ++nt){
                    mma_bf16(acc[mt][nt], ah[mt], bh[nt]);
                    mma_bf16(acc[mt][nt], ah[mt], bl[nt]);
                    mma_bf16(acc[mt][nt], al[mt], bh[nt]);
                }
        }
    }

    // ---- epilogue: bias + BN + ReLU ----
    const int r_row = lane >> 2;
    const int r_col = (lane & 3) * 2;
#pragma unroll
    for (int mt = 0; mt < 4; ++mt){
        int co0 = m0 + m_w + mt*16 + r_row;
        int co1 = co0 + 8;
        float cb0 = cb[co0], cb1 = cb[co1];
        float iv0 = bs[co0] / sqrtf(bv[co0] + 1e-3f);
        float sh0 = bbp[co0] - bm[co0]*iv0;
        float iv1 = bs[co1] / sqrtf(bv[co1] + 1e-3f);
        float sh1 = bbp[co1] - bm[co1]*iv1;
#pragma unroll
        for (int nt = 0; nt < 4; ++nt){
            int pix = p0 + n_w + nt*8 + r_col;
            float y0 = fmaxf((acc[mt][nt][0] + cb0)*iv0 + sh0, 0.f);
            float y1 = fmaxf((acc[mt][nt][1] + cb0)*iv0 + sh0, 0.f);
            float y2 = fmaxf((acc[mt][nt][2] + cb1)*iv1 + sh1, 0.f);
            float y3 = fmaxf((acc[mt][nt][3] + cb1)*iv1 + sh1, 0.f);
            if (EPI == 0){
                // write padded center copy (j=1): e = (bn*FCc+co)*PP2 + (h+1)*PW + w
                int hh2 = pix / FWw;
                int ww2 = pix - hh2*FWw;
                size_t e0 = ((size_t)(bn*FCc + co0))*PP2 + (size_t)(hh2+1)*PW + ww2;
                size_t e1 = ((size_t)(bn*FCc + co1))*PP2 + (size_t)(hh2+1)*PW + ww2;
                uint32_t hh, ll;
                split2(y0, y1, hh, ll);
                *(uint32_t*)&OutH[e0] = hh;
                *(uint32_t*)&OutL[e0] = ll;
                split2(y2, y3, hh, ll);
                *(uint32_t*)&OutH[e1] = hh;
                *(uint32_t*)&OutL[e1] = ll;
            } else {
                *(float2*)&OutF[(size_t)(bn*FCc + co0)*P2 + pix] = make_float2(y0, y1);
                *(float2*)&OutF[(size_t)(bn*FCc + co1)*P2 + pix] = make_float2(y2, y3);
            }
        }
    }
}

// ---------------- 1x1 conv3 FFMA GEMM + fused depth/transpose epilogue (FROZEN) ----------------
__global__ void conv3_gemm(const float* __restrict__ X, const float* __restrict__ Wt,
                           const float* __restrict__ cb)
{
    const int K = FCc;
    __shared__ __align__(16) float As[16][64];
    __shared__ __align__(16) float Bs[16][64];

    int tid = threadIdx.x;
    int tx = tid & 15, ty = tid >> 4;
    int n0 = blockIdx.x * 64, m0 = blockIdx.y * 64;

    float acc[4][4];
#pragma unroll
    for (int i=0;i<4;i++)
#pragma unroll
        for (int j=0;j<4;j++) acc[i][j]=0.f;

    int bcol = tid & 63, brow = tid >> 6;
    int pix = n0 + bcol;
    int bn  = pix / P2; int p = pix - bn*P2;
    const float* Xb = X + (size_t)bn*FCc*P2;

    int am = tid >> 2; int ak = (tid & 3) << 2;
    bool mvalid = (m0 + am) < C3;
    const float* Wrow = Wt + (size_t)(m0+am)*K;

    for (int k0 = 0; k0 < K; k0 += 16){
        float4 av = make_float4(0.f,0.f,0.f,0.f);
        if (mvalid) av = *(const float4*)(Wrow + k0 + ak);
        As[ak+0][am]=av.x; As[ak+1][am]=av.y; As[ak+2][am]=av.z; As[ak+3][am]=av.w;

#pragma unroll
        for (int j=0;j<4;j++){
            int kk = brow*4 + j;
            Bs[kk][bcol] = Xb[(size_t)(k0+kk)*P2 + p];
        }
        __syncthreads();

#pragma unroll
        for (int kk=0;kk<16;kk++){
            float4 a = *(const float4*)&As[kk][ty*4];
            float4 b = *(const float4*)&Bs[kk][tx*4];
            acc[0][0]+=a.x*b.x; acc[0][1]+=a.x*b.y; acc[0][2]+=a.x*b.z; acc[0][3]+=a.x*b.w;
            acc[1][0]+=a.y*b.x; acc[1][1]+=a.y*b.y; acc[1][2]+=a.y*b.z; acc[1][3]+=a.y*b.w;
            acc[2][0]+=a.z*b.x; acc[2][1]+=a.z*b.y; acc[2][2]+=a.z*b.z; acc[2][3]+=a.z*b.w;
            acc[3][0]+=a.w*b.x; acc[3][1]+=a.w*b.y; acc[3][2]+=a.w*b.z; acc[3][3]+=a.w*b.w;
        }
        __syncthreads();
    }

    // feats channels (co>=2) -> transposed featsT
#pragma unroll
    for (int i=0;i<4;i++){
        int co = m0 + ty*4 + i;
        if (co >= C3 || co < 2) continue;
        float cbv = cb[co];
#pragma unroll
        for (int j=0;j<4;j++){
            int pix2 = n0 + tx*4 + j;
            int bn2 = pix2 / P2; int p2 = pix2 - bn2*P2;
            g_featsT[((size_t)bn2*P2 + p2)*OUTC + (co-2)] = acc[i][j] + cbv;
        }
    }
    // depth gaussian (mu=co0, log_sigma=co1) — only m-tile 0, ty==0 threads
    if (m0 == 0 && ty == 0){
        float cb0 = cb[0], cb1 = cb[1];
#pragma unroll
        for (int j=0;j<4;j++){
            int pix2 = n0 + tx*4 + j;
            int bn2 = pix2 / P2; int p2 = pix2 - bn2*P2;
            float mu = acc[0][j] + cb0;
            float ls = acc[1][j] + cb1;
            float sig = expf(ls) + 1e-6f;
            float s2 = sig*sig;
            float gv[Dd];
            float sum = 0.f;
#pragma unroll
            for (int d=0; d<Dd; d++){
                float t = (1.0f + 3.0f*(float)d) - mu;
                float g = expf((-0.5f * (t*t)) / s2);
                gv[d]=g; sum += g;
            }
            float den = sum + 1e-6f;
#pragma unroll
            for (int d=0; d<Dd; d++)
                g_gbuf[(size_t)(bn2*Dd + d)*P2 + p2] = gv[d] / den;
        }
    }
}

// ---------------- scatter: one warp per point, red.v4 atomics (geometry FROZEN) ----------------
__global__ void __launch_bounds__(256) scatter_kernel(){
    int wid = threadIdx.x >> 5, lane = threadIdx.x & 31;
    int pt = blockIdx.x*8 + wid;

    int w = pt % FWw;  int t = pt / FWw;
    int h = t % FHh;   t /= FHh;
    int d = t % Dd;    t /= Dd;
    int n = t % Nn;    int b = t / Nn;
    int bn = b*Nn + n;

    int vox = -1;
    float gg = 0.f;
    if (lane == 0){
        const float* M = g_matsf + bn*24;
        float xs = __fmul_rn((float)w, __fdiv_rn(703.0f, 87.0f));
        float ys = __fmul_rn((float)h, __fdiv_rn(255.0f, 31.0f));
        float dv = 1.0f + 3.0f*(float)d;
        float px = __fsub_rn(xs, M[18]);
        float py = __fsub_rn(ys, M[19]);
        float pz = __fsub_rn(dv, M[20]);
        float q0 = fmaf(M[2], pz, fmaf(M[1], py, __fmul_rn(M[0], px)));
        float q1 = fmaf(M[5], pz, fmaf(M[4], py, __fmul_rn(M[3], px)));
        float q2 = fmaf(M[8], pz, fmaf(M[7], py, __fmul_rn(M[6], px)));
        float r0 = __fmul_rn(q0, q2);
        float r1 = __fmul_rn(q1, q2);
        float gx = __fadd_rn(fmaf(M[11], q2, fmaf(M[10], r1, __fmul_rn(M[ 9], r0))), M[21]);
        float gy = __fadd_rn(fmaf(M[14], q2, fmaf(M[13], r1, __fmul_rn(M[12], r0))), M[22]);
        float gz = __fadd_rn(fmaf(M[17], q2, fmaf(M[16], r1, __fmul_rn(M[15], r0))), M[23]);
        const float shxy = __fsub_rn(-51.0f, __fdiv_rn(0.4f, 2.0f));
        const float shz  = __fsub_rn(0.0f,  __fdiv_rn(20.0f, 2.0f));
        int ix = (int)__fdiv_rn(__fsub_rn(gx, shxy), 0.4f);
        int iy = (int)__fdiv_rn(__fsub_rn(gy, shxy), 0.4f);
        int iz = (int)__fdiv_rn(__fsub_rn(gz, shz), 20.0f);
        bool kept = (ix>=0)&&(ix<NX)&&(iy>=0)&&(iy<NY)&&(iz>=0)&&(iz<1);
        if (kept){
            vox = (b*NX + ix)*NY + iy;
            gg  = g_gbuf[(size_t)(bn*Dd + d)*P2 + h*FWw + w];
            g_maskbuf[vox] = 1;
        }
    }
    vox = __shfl_sync(0xffffffffu, vox, 0);
    gg  = __shfl_sync(0xffffffffu, gg, 0);
    if (vox >= 0){
        const float4 f = *(const float4*)&g_featsT[((size_t)bn*P2 + h*FWw + w)*OUTC + lane*4];
        float* dst = &g_bevT[(size_t)vox*OUTC + lane*4];
        red_add_v4(dst, gg*f.x, gg*f.y, gg*f.z, gg*f.w);
    }
}

// ---------------- finalize: transpose + fused mask (FROZEN) ----------------
__global__ void finalize_bev(float* __restrict__ out){
    __shared__ float tile[32][33];
    int bx = blockIdx.z;
    int b = bx >> 8, x = bx & 255;
    int c0 = blockIdx.y*32, y0 = blockIdx.x*32;
    int tx = threadIdx.x, ty = threadIdx.y;
    tile[ty][tx] = g_bevT[((size_t)bx*NY + (y0 + ty))*OUTC + (c0 + tx)];
    if (blockIdx.y == 0 && ty == 0){
        int y = y0 + tx;
        out[BEV_ELEMS + (size_t)bx*NY + y] = g_maskbuf[bx*NY + y] ? 1.0f : 0.0f;
    }
    __syncthreads();
    int c = c0 + ty, y = y0 + tx;
    out[(((size_t)b*OUTC + c)*NX + x)*NY + y] = tile[tx][ty];
}

// ---------------- launch ----------------
extern "C" void kernel_launch(void* const* d_in, const int* in_sizes, int n_in,
                              void* d_out, int out_size)
{
    const float* c2e_rot = (const float*)d_in[0];
    const float* c2e_tr  = (const float*)d_in[1];
    const float* intr    = (const float*)d_in[2];
    const float* p_rot   = (const float*)d_in[3];
    const float* p_tr    = (const float*)d_in[4];
    const float* img     = (const float*)d_in[5];
    const float* w1 = (const float*)d_in[6];
    const float* b1 = (const float*)d_in[7];
    const float* s1 = (const float*)d_in[8];
    const float* bb1= (const float*)d_in[9];
    const float* m1 = (const float*)d_in[10];
    const float* v1 = (const float*)d_in[11];
    const float* w2 = (const float*)d_in[12];
    const float* b2 = (const float*)d_in[13];
    const float* s2 = (const float*)d_in[14];
    const float* bb2= (const float*)d_in[15];
    const float* m2 = (const float*)d_in[16];
    const float* v2 = (const float*)d_in[17];
    const float* w3 = (const float*)d_in[18];
    const float* b3 = (const float*)d_in[19];
    float* out = (float*)d_out;

    void *pb2, *px1h, *px1l, *px2h, *px2l, *pw1h, *pw1l, *pw2h, *pw2l;
    cudaGetSymbolAddress(&pb2, g_buf2);
    cudaGetSymbolAddress(&px1h, g_x1h);
    cudaGetSymbolAddress(&px1l, g_x1l);
    cudaGetSymbolAddress(&px2h, g_x2h);
    cudaGetSymbolAddress(&px2l, g_x2l);
    cudaGetSymbolAddress(&pw1h, g_w1h);
    cudaGetSymbolAddress(&pw1l, g_w1l);
    cudaGetSymbolAddress(&pw2h, g_w2h);
    cudaGetSymbolAddress(&pw2l, g_w2l);
    float* buf2 = (float*)pb2;
    __nv_bfloat16* x1h = (__nv_bfloat16*)px1h;
    __nv_bfloat16* x1l = (__nv_bfloat16*)px1l;
    __nv_bfloat16* x2h = (__nv_bfloat16*)px2h;
    __nv_bfloat16* x2l = (__nv_bfloat16*)px2l;

    cudaFuncSetAttribute(conv_mma<0>, cudaFuncAttributeMaxDynamicSharedMemorySize, CONV_SMEM);
    cudaFuncSetAttribute(conv_mma<1>, cudaFuncAttributeMaxDynamicSharedMemorySize, CONV_SMEM);

    dim3 gmma(NPIX/128, FCc/128);   // (264, 2)

    // launch order: conv_mma<0> at process-launch index 3 (ncu window)
    setup_mats<<<1, 32>>>(c2e_rot, c2e_tr, intr, p_rot, p_tr);                          // 0
    prep_all<<<8192, 256>>>(w1, w2, img);                                               // 1
    zero_kernel<<<2048, 256>>>();                                                       // 2
    conv_mma<0><<<gmma, 256, CONV_SMEM>>>(x1h, x1l,
                                          (__nv_bfloat16*)pw1h, (__nv_bfloat16*)pw1l,
                                          b1, s1, bb1, m1, v1,
                                          x2h + CSZI, x2l + CSZI, nullptr);             // 3  <- profiled
    replicate_x2<<<8192, 256>>>();                                                      // 4
    conv_mma<1><<<gmma, 256, CONV_SMEM>>>(x2h, x2l,
                                          (__nv_bfloat16*)pw2h, (__nv_bfloat16*)pw2l,
                                          b2, s2, bb2, m2, v2,
                                          nullptr, nullptr, buf2);                      // 5

    dim3 g11(NPIX/64, (C3+63)/64);  // (528, 3)
    conv3_gemm<<<g11, 256>>>(buf2, w3, b3);                                             // 6

    scatter_kernel<<<NPTS/8, 256>>>();                                                  // 7

    finalize_bev<<<dim3(NY/32, OUTC/32, Bb*NX), dim3(32,32)>>>(out);                    // 8
}

// round 17
// speedup vs baseline: 1.1547x; 1.1547x over previous
#include <cuda_runtime.h>
#include <cuda_bf16.h>
#include <math.h>
#include <stdint.h>

// ---------------- problem constants ----------------
#define Bb    2
#define Nn    6
#define BN12  (Bb*Nn)          // 12
#define FCc   256
#define FHh   32
#define FWw   88
#define P2    (FHh*FWw)        // 2816
#define NPIX  (BN12*P2)        // 33792
#define Dd    20
#define OUTC  128
#define C3    (OUTC+2)         // 130
#define NX    256
#define NY    256
#define BEV_ELEMS ((size_t)Bb*OUTC*NX*NY)
#define MASK_ELEMS ((size_t)Bb*NX*NY)
#define KTOT  (FCc*9)          // 2304
#define KC    64               // k-chunk per stage
#define NSTAGE (KTOT/KC)       // 36
#define NPTS  (Bb*Nn*Dd*FHh*FWw)  // 675840

// ---------------- device scratch ----------------
__device__ __align__(16) uint32_t g_xp1[(size_t)BN12*FCc*P2];      // img split-packed
__device__ __align__(16) uint32_t g_xp2[(size_t)BN12*FCc*P2];      // conv1 out split-packed
__device__ __align__(16) __nv_bfloat16 g_c2h[(size_t)BN12*FCc*P2]; // conv2 out hi plane
__device__ __align__(16) __nv_bfloat16 g_c2l[(size_t)BN12*FCc*P2]; // conv2 out lo plane
__device__ __align__(16) __nv_bfloat16 g_w1h[(size_t)FCc*KTOT];
__device__ __align__(16) __nv_bfloat16 g_w1l[(size_t)FCc*KTOT];
__device__ __align__(16) __nv_bfloat16 g_w2h[(size_t)FCc*KTOT];
__device__ __align__(16) __nv_bfloat16 g_w2l[(size_t)FCc*KTOT];
__device__ __align__(16) __nv_bfloat16 g_w3h[(size_t)OUTC*FCc];
__device__ __align__(16) __nv_bfloat16 g_w3l[(size_t)OUTC*FCc];
__device__ __align__(16) float g_featsT[(size_t)BN12*P2*OUTC];
__device__ __align__(16) float g_gbuf[(size_t)BN12*Dd*P2];
__device__ __align__(16) float g_bevT[(size_t)Bb*NX*NY*OUTC];
__device__ __align__(16) unsigned char g_maskbuf[Bb*NX*NY];
__device__ float g_matsf[BN12*24];

// ---------------- helpers ----------------
__device__ __forceinline__ uint32_t smem_u32(const void* p){
    uint32_t a;
    asm("{ .reg .u64 t; cvta.to.shared.u64 t, %1; cvt.u32.u64 %0, t; }" : "=r"(a) : "l"(p));
    return a;
}
__device__ __forceinline__ void ldsm_x4(uint32_t &r0,uint32_t &r1,uint32_t &r2,uint32_t &r3, uint32_t a){
    asm volatile("ldmatrix.sync.aligned.m8n8.x4.shared.b16 {%0,%1,%2,%3}, [%4];"
        : "=r"(r0),"=r"(r1),"=r"(r2),"=r"(r3) : "r"(a));
}
__device__ __forceinline__ void ldsm_x4_t(uint32_t &r0,uint32_t &r1,uint32_t &r2,uint32_t &r3, uint32_t a){
    asm volatile("ldmatrix.sync.aligned.m8n8.x4.trans.shared.b16 {%0,%1,%2,%3}, [%4];"
        : "=r"(r0),"=r"(r1),"=r"(r2),"=r"(r3) : "r"(a));
}
__device__ __forceinline__ void mma_bf16(float* c, const uint32_t* a, const uint32_t* b){
    asm volatile("mma.sync.aligned.m16n8k16.row.col.f32.bf16.bf16.f32 "
        "{%0,%1,%2,%3}, {%4,%5,%6,%7}, {%8,%9}, {%0,%1,%2,%3};"
        : "+f"(c[0]),"+f"(c[1]),"+f"(c[2]),"+f"(c[3])
        : "r"(a[0]),"r"(a[1]),"r"(a[2]),"r"(a[3]), "r"(b[0]),"r"(b[1]));
}
__device__ __forceinline__ void cp_async16(uint32_t dst, const void* src){
    asm volatile("cp.async.cg.shared.global [%0], [%1], 16;" :: "r"(dst), "l"(src));
}
__device__ __forceinline__ void cp_commit(){ asm volatile("cp.async.commit_group;"); }
__device__ __forceinline__ void cp_wait0(){ asm volatile("cp.async.wait_group 0;"); }
__device__ __forceinline__ void red_add_v4(float* p, float x, float y, float z, float w){
    asm volatile("red.global.add.v4.f32 [%0], {%1,%2,%3,%4};"
                 :: "l"(p), "f"(x), "f"(y), "f"(z), "f"(w) : "memory");
}
__device__ __forceinline__ uint32_t pack_split(float x){
    __nv_bfloat16 h = __float2bfloat16(x);
    float hf = __bfloat162float(h);
    __nv_bfloat16 l = __float2bfloat16(x - hf);
    return (uint32_t)__bfloat16_as_ushort(h) | ((uint32_t)__bfloat16_as_ushort(l) << 16);
}
__device__ __forceinline__ void split2(float a, float b, uint32_t &hh, uint32_t &ll){
    __nv_bfloat16 ha = __float2bfloat16(a);
    __nv_bfloat16 hb = __float2bfloat16(b);
    __nv_bfloat16 la = __float2bfloat16(a - __bfloat162float(ha));
    __nv_bfloat16 lb = __float2bfloat16(b - __bfloat162float(hb));
    hh = (uint32_t)__bfloat16_as_ushort(ha) | ((uint32_t)__bfloat16_as_ushort(hb) << 16);
    ll = (uint32_t)__bfloat16_as_ushort(la) | ((uint32_t)__bfloat16_as_ushort(lb) << 16);
}

// ---------------- f32 3x3 inverse, cuSOLVER-style (FROZEN) ----------------
__device__ __forceinline__ void lu_inv3x3_cusolver(const float* A, float* X){
    float a00=A[0],a01=A[1],a02=A[2],a10=A[3],a11=A[4],a12=A[5],a20=A[6],a21=A[7],a22=A[8];
    float r0 = __fdiv_rn(1.0f, a00);
    float l10 = __fmul_rn(a10, r0);
    float l20 = __fmul_rn(a20, r0);
    float u11 = fmaf(-l10, a01, a11);
    float u12 = fmaf(-l10, a02, a12);
    float t21 = fmaf(-l20, a01, a21);
    float u22t= fmaf(-l20, a02, a22);
    float r1 = __fdiv_rn(1.0f, u11);
    float l21 = __fmul_rn(t21, r1);
    float u22 = fmaf(-l21, u12, u22t);
    float r2 = __fdiv_rn(1.0f, u22);
#pragma unroll
    for (int j=0;j<3;j++){
        float e0 = (j==0)?1.f:0.f, e1=(j==1)?1.f:0.f, e2=(j==2)?1.f:0.f;
        float y0 = e0;
        float y1 = fmaf(-l10, y0, e1);
        float y2 = fmaf(-l21, y1, fmaf(-l20, y0, e2));
        float x2 = __fmul_rn(y2, r2);
        float x1 = __fmul_rn(fmaf(-u12, x2, y1), r1);
        float x0 = __fmul_rn(fmaf(-a02, x2, fmaf(-a01, x1, y0)), r0);
        X[0*3+j]=x0; X[1*3+j]=x1; X[2*3+j]=x2;
    }
}

__global__ void setup_mats(const float* __restrict__ rot, const float* __restrict__ tr,
                           const float* __restrict__ intr,
                           const float* __restrict__ prot, const float* __restrict__ ptr_){
    int i = threadIdx.x;
    if (i >= BN12) return;
    float IP[9], IK[9];
    lu_inv3x3_cusolver(prot + i*9, IP);
    lu_inv3x3_cusolver(intr + i*9, IK);
    float* M = g_matsf + i*24;
#pragma unroll
    for (int j=0;j<9;j++) M[j]=IP[j];
#pragma unroll
    for (int r=0;r<3;r++)
#pragma unroll
        for (int c=0;c<3;c++){
            float acc = __fmul_rn(rot[i*9+r*3+0], IK[0*3+c]);
            acc = fmaf(rot[i*9+r*3+1], IK[1*3+c], acc);
            acc = fmaf(rot[i*9+r*3+2], IK[2*3+c], acc);
            M[9+r*3+c]=acc;
        }
#pragma unroll
    for (int j=0;j<3;j++){ M[18+j]=ptr_[i*3+j]; M[21+j]=tr[i*3+j]; }
}

// ---------------- fused prep: weight splits (w1,w2,w3 feats) + img split-pack ----------------
__global__ void prep_all(const float* __restrict__ w1, const float* __restrict__ w2,
                         const float* __restrict__ w3, const float* __restrict__ img){
    int i = blockIdx.x*blockDim.x + threadIdx.x;
    int stride = gridDim.x*blockDim.x;
    const int NW = FCc*KTOT;
    for (int k = i; k < NW; k += stride){
        float x1 = w1[k];
        __nv_bfloat16 h1 = __float2bfloat16(x1);
        g_w1h[k] = h1;
        g_w1l[k] = __float2bfloat16(x1 - __bfloat162float(h1));
        float x2 = w2[k];
        __nv_bfloat16 h2 = __float2bfloat16(x2);
        g_w2h[k] = h2;
        g_w2l[k] = __float2bfloat16(x2 - __bfloat162float(h2));
    }
    const int NW3 = OUTC*FCc;
    for (int k = i; k < NW3; k += stride){
        float x3 = w3[2*FCc + k];   // feats rows start at channel 2
        __nv_bfloat16 h3 = __float2bfloat16(x3);
        g_w3h[k] = h3;
        g_w3l[k] = __float2bfloat16(x3 - __bfloat162float(h3));
    }
    const int NI = BN12*FCc*P2;
    for (int k = i; k < NI; k += stride) g_xp1[k] = pack_split(img[k]);
}

__global__ void zero_kernel(){
    size_t tid = (size_t)blockIdx.x*blockDim.x + threadIdx.x;
    size_t stride = (size_t)gridDim.x*blockDim.x;
    float4* bp = (float4*)g_bevT;
    const size_t n4 = BEV_ELEMS/4;
    for (size_t i=tid;i<n4;i+=stride) bp[i]=make_float4(0.f,0.f,0.f,0.f);
    uint4* mp = (uint4*)g_maskbuf;
    const size_t nm = MASK_ELEMS/16;
    for (size_t i=tid;i<nm;i+=stride) mp[i]=make_uint4(0u,0u,0u,0u);
}

// ---------------- bf16-split implicit conv GEMM, 2 CTAs/SM single-stage (R15, FROZEN) ----------------
#define OFF_AHI   0
#define OFF_ALO   16384
#define OFF_BHI   32768
#define OFF_BLO   49152
#define STAGE_BYTES 65536
#define KTAB_OFF  STAGE_BYTES              // 65536
#define CONV_SMEM (KTAB_OFF + KTOT*4)      // 74752

template<int EPI> // 0: packed split u32 out ; 1: hi/lo bf16 plane out
__global__ void __launch_bounds__(256, 2)
conv_mma(const uint32_t* __restrict__ Xp,
         const __nv_bfloat16* __restrict__ Wh, const __nv_bfloat16* __restrict__ Wl,
         const float* __restrict__ cb,
         const float* __restrict__ bs, const float* __restrict__ bbp,
         const float* __restrict__ bm, const float* __restrict__ bv,
         uint32_t* __restrict__ Yout,
         __nv_bfloat16* __restrict__ OutH, __nv_bfloat16* __restrict__ OutL)
{
    extern __shared__ char smbuf[];
    const uint32_t sb = smem_u32(smbuf);
    uint32_t* ktab = (uint32_t*)(smbuf + KTAB_OFF);
    const int tid = threadIdx.x;
    const int wid = tid >> 5;
    const int lane = tid & 31;

    const int tileP = blockIdx.x;              // 0..263
    const int m0 = blockIdx.y * 128;           // co tile base
    const int bn = tileP / 22;
    const int p0 = (tileP - bn*22) * 128;
    const uint32_t* Xb = Xp + (size_t)bn * FCc * P2;

    // ---- build k-offset table ----
    for (int k = tid; k < KTOT; k += 256){
        int ci = k / 9; int r = k - 9*ci;
        int kh = r / 3; int kw = r - 3*kh;
        int off = ci*P2 + (kh-1)*FWw + (kw-1);
        ktab[k] = ((uint32_t)(kh*3+kw) << 28) | (uint32_t)(off + 4096);
    }

    // warp tiling: 2 (M) x 4 (N)
    const int wm = wid & 1, wn = wid >> 1;
    const int m_w = wm * 64, n_w = wn * 32;

    float acc[4][4][4];
#pragma unroll
    for (int a=0;a<4;a++)
#pragma unroll
        for (int b=0;b<4;b++)
#pragma unroll
            for (int c=0;c<4;c++) acc[a][b][c]=0.f;

    // B loader fixed coords + per-pixel 9-bit validity masks
    int p_i[4];
    uint32_t pm_i[4];
#pragma unroll
    for (int i=0;i<4;i++){
        int pl = lane + 32*i;
        p_i[i] = p0 + pl;
        int h = p_i[i] / FWw;
        int w = p_i[i] - h*FWw;
        uint32_t m9 = 0;
#pragma unroll
        for (int kh=0;kh<3;kh++)
#pragma unroll
            for (int kw=0;kw<3;kw++){
                int hh = h + kh - 1, ww = w + kw - 1;
                if (hh>=0 && hh<FHh && ww>=0 && ww<FWw) m9 |= 1u << (kh*3+kw);
            }
        pm_i[i] = m9;
    }
    // A cp.async coords
    const int a_row  = tid >> 1;
    const int a_half = (tid & 1) * 64;
    const __nv_bfloat16* wh_row = Wh + (size_t)(m0 + a_row)*KTOT + (a_half >> 1);
    const __nv_bfloat16* wl_row = Wl + (size_t)(m0 + a_row)*KTOT + (a_half >> 1);

    // ldmatrix hoisted address components
    const int lr = lane & 15;
    const int khalf16 = (lane >> 4) * 16;
    const uint32_t lx = (uint32_t)((lane & 7) << 4);
    uint32_t kxv[4];
#pragma unroll
    for (int kk=0;kk<4;kk++) kxv[kk] = (uint32_t)(kk*32 + khalf16) ^ lx;
    uint32_t amb[4];
#pragma unroll
    for (int mt=0;mt<4;mt++) amb[mt] = (uint32_t)((m_w + mt*16 + lr)*128);
    uint32_t bnb[2];
#pragma unroll
    for (int nt2=0;nt2<2;nt2++) bnb[nt2] = (uint32_t)((n_w + nt2*16 + lr)*128);
    const uint32_t bxor = (uint32_t)(wid*16) ^ lx;
    uint32_t asto[4];
#pragma unroll
    for (int i=0;i<4;i++)
        asto[i] = (uint32_t)(a_row*128) + ((uint32_t)(a_half + i*16) ^ ((uint32_t)(a_row & 7) << 4));

#pragma unroll 1
    for (int s = 0; s < NSTAGE; ++s){
        __syncthreads();            // compute(s-1) done, safe to overwrite

        // ---- A: cp.async weights into smem ----
        {
            const __nv_bfloat16* srcH = wh_row + s*KC;
            const __nv_bfloat16* srcL = wl_row + s*KC;
#pragma unroll
            for (int i=0;i<4;i++){
                cp_async16(sb + OFF_AHI + asto[i], srcH + i*8);
                cp_async16(sb + OFF_ALO + asto[i], srcL + i*8);
            }
            cp_commit();
        }
        // ---- B: gather + pack + store ----
        {
            const uint32_t* tp = &ktab[s*KC + wid*8];
            uint4 t0 = *(const uint4*)tp;
            uint4 t1 = *(const uint4*)(tp + 4);
            uint32_t te[8] = {t0.x,t0.y,t0.z,t0.w,t1.x,t1.y,t1.z,t1.w};
            uint32_t braw[32];
#pragma unroll
            for (int i=0;i<4;i++){
#pragma unroll
                for (int j=0;j<8;j++){
                    uint32_t e = te[j];
                    int off = (int)(e & 0x0fffffffu) - 4096;
                    bool valid = (pm_i[i] >> (e >> 28)) & 1u;
                    braw[i*8+j] = valid ? Xb[p_i[i] + off] : 0u;
                }
            }
#pragma unroll
            for (int i=0;i<4;i++){
                uint32_t hp[4], lp[4];
#pragma unroll
                for (int q=0;q<4;q++){
                    uint32_t u0 = braw[i*8+q*2+0], u1 = braw[i*8+q*2+1];
                    hp[q] = (u0 & 0xffffu) | ((u1 & 0xffffu) << 16);
                    lp[q] = (u0 >> 16)     | ((u1 >> 16) << 16);
                }
                uint32_t sw = (uint32_t)((lane + 32*i)*128) + bxor;
                *(uint4*)(smbuf + OFF_BHI + sw) = make_uint4(hp[0],hp[1],hp[2],hp[3]);
                *(uint4*)(smbuf + OFF_BLO + sw) = make_uint4(lp[0],lp[1],lp[2],lp[3]);
            }
        }
        cp_wait0();                 // A landed
        __syncthreads();            // tiles visible

        // ---- compute stage s: 4 k-steps of 16 ----
#pragma unroll
        for (int kk = 0; kk < 4; ++kk){
            uint32_t ah[4][4], al[4][4];
#pragma unroll
            for (int mt = 0; mt < 4; ++mt){
                uint32_t a = sb + OFF_AHI + amb[mt] + kxv[kk];
                ldsm_x4(ah[mt][0], ah[mt][1], ah[mt][2], ah[mt][3], a);
                ldsm_x4(al[mt][0], al[mt][1], al[mt][2], al[mt][3], a + 16384);
            }
            uint32_t bh[4][2], bl[4][2];
#pragma unroll
            for (int nt2 = 0; nt2 < 2; ++nt2){
                uint32_t a = sb + OFF_BHI + bnb[nt2] + kxv[kk];
                uint32_t r0,r1,r2,r3;
                ldsm_x4(r0,r1,r2,r3, a);
                bh[nt2*2+0][0]=r0; bh[nt2*2+0][1]=r2;
                bh[nt2*2+1][0]=r1; bh[nt2*2+1][1]=r3;
                ldsm_x4(r0,r1,r2,r3, a + 16384);
                bl[nt2*2+0][0]=r0; bl[nt2*2+0][1]=r2;
                bl[nt2*2+1][0]=r1; bl[nt2*2+1][1]=r3;
            }
#pragma unroll
            for (int mt = 0; mt < 4; ++mt)
#pragma unroll
                for (int nt = 0; nt < 4; ++nt){
                    mma_bf16(acc[mt][nt], ah[mt], bh[nt]);
                    mma_bf16(acc[mt][nt], ah[mt], bl[nt]);
                    mma_bf16(acc[mt][nt], al[mt], bh[nt]);
                }
        }
    }

    // ---- epilogue: bias + BN + ReLU ----
    const int r_row = lane >> 2;
    const int r_col = (lane & 3) * 2;
#pragma unroll
    for (int mt = 0; mt < 4; ++mt){
        int co0 = m0 + m_w + mt*16 + r_row;
        int co1 = co0 + 8;
        float cb0 = cb[co0], cb1 = cb[co1];
        float iv0 = bs[co0] / sqrtf(bv[co0] + 1e-3f);
        float sh0 = bbp[co0] - bm[co0]*iv0;
        float iv1 = bs[co1] / sqrtf(bv[co1] + 1e-3f);
        float sh1 = bbp[co1] - bm[co1]*iv1;
#pragma unroll
        for (int nt = 0; nt < 4; ++nt){
            int pix = p0 + n_w + nt*8 + r_col;
            float y0 = fmaxf((acc[mt][nt][0] + cb0)*iv0 + sh0, 0.f);
            float y1 = fmaxf((acc[mt][nt][1] + cb0)*iv0 + sh0, 0.f);
            float y2 = fmaxf((acc[mt][nt][2] + cb1)*iv1 + sh1, 0.f);
            float y3 = fmaxf((acc[mt][nt][3] + cb1)*iv1 + sh1, 0.f);
            if (EPI == 0){
                *(uint2*)&Yout[(size_t)(bn*FCc + co0)*P2 + pix] = make_uint2(pack_split(y0), pack_split(y1));
                *(uint2*)&Yout[(size_t)(bn*FCc + co1)*P2 + pix] = make_uint2(pack_split(y2), pack_split(y3));
            } else {
                uint32_t hh, ll;
                size_t e0 = (size_t)(bn*FCc + co0)*P2 + pix;
                size_t e1 = (size_t)(bn*FCc + co1)*P2 + pix;
                split2(y0, y1, hh, ll);
                *(uint32_t*)&OutH[e0] = hh;
                *(uint32_t*)&OutL[e0] = ll;
                split2(y2, y3, hh, ll);
                *(uint32_t*)&OutH[e1] = hh;
                *(uint32_t*)&OutL[e1] = ll;
            }
        }
    }
}

// ---------------- conv3 feats (128 ch) via bf16-split MMA, K=256, all-async B ----------------
#define C3_SMEM  65536   // A 2x16KB + B 2x16KB

__global__ void __launch_bounds__(256, 2)
conv3_mma(const __nv_bfloat16* __restrict__ XH, const __nv_bfloat16* __restrict__ XL,
          const float* __restrict__ cb3)
{
    extern __shared__ char smbuf[];
    const uint32_t sb = smem_u32(smbuf);
    const int tid = threadIdx.x;
    const int wid = tid >> 5;
    const int lane = tid & 31;

    const int tileP = blockIdx.x;              // 0..263
    const int bn = tileP / 22;
    const int p0 = (tileP - bn*22) * 128;

    const int wm = wid & 1, wn = wid >> 1;
    const int m_w = wm * 64, n_w = wn * 32;

    float acc[4][4][4];
#pragma unroll
    for (int a=0;a<4;a++)
#pragma unroll
        for (int b=0;b<4;b++)
#pragma unroll
            for (int c=0;c<4;c++) acc[a][b][c]=0.f;

    // A producer (weights w3 feats): row = tid>>1, half-row
    const int a_row  = tid >> 1;
    const int a_half = (tid & 1) * 64;
    const __nv_bfloat16* wh_row = g_w3h + (size_t)a_row*FCc + (a_half >> 1);
    const __nv_bfloat16* wl_row = g_w3l + (size_t)a_row*FCc + (a_half >> 1);
    uint32_t asto[4];
#pragma unroll
    for (int i=0;i<4;i++)
        asto[i] = (uint32_t)(a_row*128) + ((uint32_t)(a_half + i*16) ^ ((uint32_t)(a_row & 7) << 4));

    // B producer: plane/pixel-group scheme (R16-validated): k row = wid*8+i
    const int pg = lane & 15;
    const int plane = lane >> 4;
    const __nv_bfloat16* Xpb = (plane ? XL : XH) + (size_t)bn * FCc * P2 + p0 + pg*8;
    const uint32_t dstb2 = sb + OFF_BHI + (uint32_t)(plane*16384);
    const uint32_t pgx = (uint32_t)(pg << 4);

    // consumer A ldsm
    const int lr = lane & 15;
    const int khalf16 = (lane >> 4) * 16;
    const uint32_t lx = (uint32_t)((lane & 7) << 4);
    uint32_t kxv[4];
#pragma unroll
    for (int kk=0;kk<4;kk++) kxv[kk] = (uint32_t)(kk*32 + khalf16) ^ lx;
    uint32_t amb[4];
#pragma unroll
    for (int mt=0;mt<4;mt++) amb[mt] = (uint32_t)((m_w + mt*16 + lr)*128);
    // consumer B trans-ldsm (R16-validated mapping)
    const int setq = lane >> 3, rr = lane & 7;
    const uint32_t bconst = (uint32_t)((((setq & 2) ? 8 : 0) + rr) * 256);
    uint32_t pbx[2];
#pragma unroll
    for (int nt2=0;nt2<2;nt2++)
        pbx[nt2] = ((uint32_t)((n_w + nt2*16 + ((setq & 1) ? 8 : 0)) * 2)) ^ ((uint32_t)(rr << 4));
    const uint32_t sbB = sb + OFF_BHI;

#pragma unroll 1
    for (int s = 0; s < 4; ++s){        // K = 256 = 4 x 64
        const int k0 = s * KC;
        __syncthreads();

        // A: cp.async weights
        {
            const __nv_bfloat16* srcH = wh_row + s*KC;
            const __nv_bfloat16* srcL = wl_row + s*KC;
#pragma unroll
            for (int i=0;i<4;i++){
                cp_async16(sb + OFF_AHI + asto[i], srcH + i*8);
                cp_async16(sb + OFF_ALO + asto[i], srcL + i*8);
            }
        }
        // B: cp.async contiguous rows from conv2-output plane
#pragma unroll
        for (int i=0;i<8;i++){
            int kr = wid*8 + i;
            uint32_t dst = dstb2 + (uint32_t)(kr*256) + (pgx ^ ((uint32_t)i << 4));
            cp_async16(dst, Xpb + (size_t)(k0 + kr)*P2);
        }
        cp_commit();
        cp_wait0();
        __syncthreads();

        // compute
#pragma unroll
        for (int kk = 0; kk < 4; ++kk){
            uint32_t ah[4][4], al[4][4];
#pragma unroll
            for (int mt = 0; mt < 4; ++mt){
                uint32_t a = sb + OFF_AHI + amb[mt] + kxv[kk];
                ldsm_x4(ah[mt][0], ah[mt][1], ah[mt][2], ah[mt][3], a);
                ldsm_x4(al[mt][0], al[mt][1], al[mt][2], al[mt][3], a + 16384);
            }
            uint32_t bh[4][2], bl[4][2];
#pragma unroll
            for (int nt2 = 0; nt2 < 2; ++nt2){
                uint32_t a = sbB + (uint32_t)(kk*4096) + bconst + pbx[nt2];
                uint32_t r0,r1,r2,r3;
                ldsm_x4_t(r0,r1,r2,r3, a);
                bh[nt2*2+0][0]=r0; bh[nt2*2+0][1]=r2;
                bh[nt2*2+1][0]=r1; bh[nt2*2+1][1]=r3;
                ldsm_x4_t(r0,r1,r2,r3, a + 16384);
                bl[nt2*2+0][0]=r0; bl[nt2*2+0][1]=r2;
                bl[nt2*2+1][0]=r1; bl[nt2*2+1][1]=r3;
            }
#pragma unroll
            for (int mt = 0; mt < 4; ++mt)
#pragma unroll
                for (int nt = 0; nt < 4; ++nt){
                    mma_bf16(acc[mt][nt], ah[mt], bh[nt]);
                    mma_bf16(acc[mt][nt], ah[mt], bl[nt]);
                    mma_bf16(acc[mt][nt], al[mt], bh[nt]);
                }
        }
    }

    // epilogue: bias, write featsT[(bn*P2+pix)*128 + co]
    const int r_row = lane >> 2;
    const int r_col = (lane & 3) * 2;
    float* fT = g_featsT + (size_t)bn*P2*OUTC;
#pragma unroll
    for (int mt = 0; mt < 4; ++mt){
        int co0 = m_w + mt*16 + r_row;
        int co1 = co0 + 8;
        float cb0 = cb3[co0 + 2], cb1 = cb3[co1 + 2];
#pragma unroll
        for (int nt = 0; nt < 4; ++nt){
            int pix = p0 + n_w + nt*8 + r_col;
            fT[(size_t)pix*OUTC + co0]     = acc[mt][nt][0] + cb0;
            fT[(size_t)(pix+1)*OUTC + co0] = acc[mt][nt][1] + cb0;
            fT[(size_t)pix*OUTC + co1]     = acc[mt][nt][2] + cb1;
            fT[(size_t)(pix+1)*OUTC + co1] = acc[mt][nt][3] + cb1;
        }
    }
}

// ---------------- depth mu/log_sigma + gaussian ----------------
__global__ void depth_kernel(const __nv_bfloat16* __restrict__ XH,
                             const __nv_bfloat16* __restrict__ XL,
                             const float* __restrict__ w3, const float* __restrict__ b3){
    int idx = blockIdx.x*blockDim.x + threadIdx.x;
    if (idx >= NPIX) return;
    int bn = idx / P2; int p = idx - bn*P2;
    const __nv_bfloat16* bh = XH + (size_t)bn*FCc*P2 + p;
    const __nv_bfloat16* bl = XL + (size_t)bn*FCc*P2 + p;
    float mu = 0.f, ls = 0.f;
#pragma unroll 8
    for (int k = 0; k < FCc; ++k){
        float x = __bfloat162float(bh[(size_t)k*P2]) + __bfloat162float(bl[(size_t)k*P2]);
        mu = fmaf(x, w3[k], mu);
        ls = fmaf(x, w3[FCc + k], ls);
    }
    mu += b3[0];
    ls += b3[1];
    float sig = expf(ls) + 1e-6f;
    float s2 = sig*sig;
    float gv[Dd];
    float sum = 0.f;
#pragma unroll
    for (int d=0; d<Dd; d++){
        float t = (1.0f + 3.0f*(float)d) - mu;
        float g = expf((-0.5f * (t*t)) / s2);
        gv[d]=g; sum += g;
    }
    float den = sum + 1e-6f;
#pragma unroll
    for (int d=0; d<Dd; d++)
        g_gbuf[(size_t)(bn*Dd + d)*P2 + p] = gv[d] / den;
}

// ---------------- scatter: one warp per point, red.v4 atomics (geometry FROZEN) ----------------
__global__ void __launch_bounds__(256) scatter_kernel(){
    int wid = threadIdx.x >> 5, lane = threadIdx.x & 31;
    int pt = blockIdx.x*8 + wid;

    int w = pt % FWw;  int t = pt / FWw;
    int h = t % FHh;   t /= FHh;
    int d = t % Dd;    t /= Dd;
    int n = t % Nn;    int b = t / Nn;
    int bn = b*Nn + n;

    int vox = -1;
    float gg = 0.f;
    if (lane == 0){
        const float* M = g_matsf + bn*24;
        float xs = __fmul_rn((float)w, __fdiv_rn(703.0f, 87.0f));
        float ys = __fmul_rn((float)h, __fdiv_rn(255.0f, 31.0f));
        float dv = 1.0f + 3.0f*(float)d;
        float px = __fsub_rn(xs, M[18]);
        float py = __fsub_rn(ys, M[19]);
        float pz = __fsub_rn(dv, M[20]);
        float q0 = fmaf(M[2], pz, fmaf(M[1], py, __fmul_rn(M[0], px)));
        float q1 = fmaf(M[5], pz, fmaf(M[4], py, __fmul_rn(M[3], px)));
        float q2 = fmaf(M[8], pz, fmaf(M[7], py, __fmul_rn(M[6], px)));
        float r0 = __fmul_rn(q0, q2);
        float r1 = __fmul_rn(q1, q2);
        float gx = __fadd_rn(fmaf(M[11], q2, fmaf(M[10], r1, __fmul_rn(M[ 9], r0))), M[21]);
        float gy = __fadd_rn(fmaf(M[14], q2, fmaf(M[13], r1, __fmul_rn(M[12], r0))), M[22]);
        float gz = __fadd_rn(fmaf(M[17], q2, fmaf(M[16], r1, __fmul_rn(M[15], r0))), M[23]);
        const float shxy = __fsub_rn(-51.0f, __fdiv_rn(0.4f, 2.0f));
        const float shz  = __fsub_rn(0.0f,  __fdiv_rn(20.0f, 2.0f));
        int ix = (int)__fdiv_rn(__fsub_rn(gx, shxy), 0.4f);
        int iy = (int)__fdiv_rn(__fsub_rn(gy, shxy), 0.4f);
        int iz = (int)__fdiv_rn(__fsub_rn(gz, shz), 20.0f);
        bool kept = (ix>=0)&&(ix<NX)&&(iy>=0)&&(iy<NY)&&(iz>=0)&&(iz<1);
        if (kept){
            vox = (b*NX + ix)*NY + iy;
            gg  = g_gbuf[(size_t)(bn*Dd + d)*P2 + h*FWw + w];
            g_maskbuf[vox] = 1;
        }
    }
    vox = __shfl_sync(0xffffffffu, vox, 0);
    gg  = __shfl_sync(0xffffffffu, gg, 0);
    if (vox >= 0){
        const float4 f = *(const float4*)&g_featsT[((size_t)bn*P2 + h*FWw + w)*OUTC + lane*4];
        float* dst = &g_bevT[(size_t)vox*OUTC + lane*4];
        red_add_v4(dst, gg*f.x, gg*f.y, gg*f.z, gg*f.w);
    }
}

// ---------------- finalize: transpose + fused mask (FROZEN) ----------------
__global__ void finalize_bev(float* __restrict__ out){
    __shared__ float tile[32][33];
    int bx = blockIdx.z;
    int b = bx >> 8, x = bx & 255;
    int c0 = blockIdx.y*32, y0 = blockIdx.x*32;
    int tx = threadIdx.x, ty = threadIdx.y;
    tile[ty][tx] = g_bevT[((size_t)bx*NY + (y0 + ty))*OUTC + (c0 + tx)];
    if (blockIdx.y == 0 && ty == 0){
        int y = y0 + tx;
        out[BEV_ELEMS + (size_t)bx*NY + y] = g_maskbuf[bx*NY + y] ? 1.0f : 0.0f;
    }
    __syncthreads();
    int c = c0 + ty, y = y0 + tx;
    out[(((size_t)b*OUTC + c)*NX + x)*NY + y] = tile[tx][ty];
}

// ---------------- launch ----------------
extern "C" void kernel_launch(void* const* d_in, const int* in_sizes, int n_in,
                              void* d_out, int out_size)
{
    const float* c2e_rot = (const float*)d_in[0];
    const float* c2e_tr  = (const float*)d_in[1];
    const float* intr    = (const float*)d_in[2];
    const float* p_rot   = (const float*)d_in[3];
    const float* p_tr    = (const float*)d_in[4];
    const float* img     = (const float*)d_in[5];
    const float* w1 = (const float*)d_in[6];
    const float* b1 = (const float*)d_in[7];
    const float* s1 = (const float*)d_in[8];
    const float* bb1= (const float*)d_in[9];
    const float* m1 = (const float*)d_in[10];
    const float* v1 = (const float*)d_in[11];
    const float* w2 = (const float*)d_in[12];
    const float* b2 = (const float*)d_in[13];
    const float* s2 = (const float*)d_in[14];
    const float* bb2= (const float*)d_in[15];
    const float* m2 = (const float*)d_in[16];
    const float* v2 = (const float*)d_in[17];
    const float* w3 = (const float*)d_in[18];
    const float* b3 = (const float*)d_in[19];
    float* out = (float*)d_out;

    void *pxp1, *pxp2, *pc2h, *pc2l, *pw1h, *pw1l, *pw2h, *pw2l;
    cudaGetSymbolAddress(&pxp1, g_xp1);
    cudaGetSymbolAddress(&pxp2, g_xp2);
    cudaGetSymbolAddress(&pc2h, g_c2h);
    cudaGetSymbolAddress(&pc2l, g_c2l);
    cudaGetSymbolAddress(&pw1h, g_w1h);
    cudaGetSymbolAddress(&pw1l, g_w1l);
    cudaGetSymbolAddress(&pw2h, g_w2h);
    cudaGetSymbolAddress(&pw2l, g_w2l);
    uint32_t* xp1 = (uint32_t*)pxp1;
    uint32_t* xp2 = (uint32_t*)pxp2;
    __nv_bfloat16* c2h = (__nv_bfloat16*)pc2h;
    __nv_bfloat16* c2l = (__nv_bfloat16*)pc2l;

    cudaFuncSetAttribute(conv_mma<0>, cudaFuncAttributeMaxDynamicSharedMemorySize, CONV_SMEM);
    cudaFuncSetAttribute(conv_mma<1>, cudaFuncAttributeMaxDynamicSharedMemorySize, CONV_SMEM);
    cudaFuncSetAttribute(conv3_mma, cudaFuncAttributeMaxDynamicSharedMemorySize, C3_SMEM);

    dim3 gmma(NPIX/128, FCc/128);   // (264, 2)

    // launch order: conv_mma<0> at process-launch index 3 (ncu window)
    setup_mats<<<1, 32>>>(c2e_rot, c2e_tr, intr, p_rot, p_tr);                          // 0
    prep_all<<<4096, 256>>>(w1, w2, w3, img);                                           // 1
    zero_kernel<<<2048, 256>>>();                                                       // 2
    conv_mma<0><<<gmma, 256, CONV_SMEM>>>(xp1, (__nv_bfloat16*)pw1h, (__nv_bfloat16*)pw1l,
                                          b1, s1, bb1, m1, v1, xp2, nullptr, nullptr);  // 3  <- profiled
    conv_mma<1><<<gmma, 256, CONV_SMEM>>>(xp2, (__nv_bfloat16*)pw2h, (__nv_bfloat16*)pw2l,
                                          b2, s2, bb2, m2, v2, nullptr, c2h, c2l);      // 4
    conv3_mma<<<NPIX/128, 256, C3_SMEM>>>(c2h, c2l, b3);                                // 5
    depth_kernel<<<(NPIX+255)/256, 256>>>(c2h, c2l, w3, b3);                            // 6
    scatter_kernel<<<NPTS/8, 256>>>();                                                  // 7
    finalize_bev<<<dim3(NY/32, OUTC/32, Bb*NX), dim3(32,32)>>>(out);                    // 8
}